// round 15
// baseline (speedup 1.0000x reference)
#include <cuda_runtime.h>
#include <cuda_fp16.h>
#include <mma.h>
using namespace nvcuda;

#define D 64
#define N_MAX 50048
#define E_MAX 800000
#define SCAN_BLK 256
#define KV_ROW 768   // bytes: [k_alpha|k_beta half 256B][v_t fp32 256B][v_x fp32 256B]

// ---------------- device scratch (static, allowed) ----------------
__device__ __align__(16) __half g_q [N_MAX * 128];     // [q_alpha|q_beta] 256B rows
__device__ __align__(16) char   g_kv[N_MAX * KV_ROW];  // mixed row, see above

// CSR-style bucketing of edges by destination (row).
__device__ int g_cnt[N_MAX];      // in-degree (zero at load; scan re-zeros)
__device__ int g_start[N_MAX];    // bucket base
__device__ int g_cursor[N_MAX];   // bucket END (start + cnt)
__device__ int g_sc[E_MAX + 8];   // BYTE OFFSET of src node's kv row (c*768); slack zeroed
__device__ int g_rank[E_MAX];     // within-bucket rank (from hist)
__device__ int g_total;           // ticket counter

// ---------------- kernel 1: projections via HMMA + fused histogram ------
struct PArgs {
    const float* in[6];
    const float* W[6];
    const float* b[6];
};

#define LDA 72
#define LDW 72
#define LDC 68

__global__ __launch_bounds__(256) void proj_hist_kernel(
    PArgs a, const int* __restrict__ ei, int n, int e, int nblk_proj) {
    __shared__ __align__(16) char sbuf[34816];

    int p   = blockIdx.y;
    int tid = threadIdx.x;

    // ---------------- histogram slice (hides under tensor work) ----------
    if (p == 6) {
        if (tid == 0 && blockIdx.x == 0) g_total = 0;
        int i = blockIdx.x * 256 + tid;       // thread handles 8 edges = 2 int4
        const int4* e4 = (const int4*)ei;
        int ne4 = e >> 2;
        #pragma unroll
        for (int t = 0; t < 2; t++) {
            int idx4 = i * 2 + t;
            if (idx4 < ne4) {
                int4 r = __ldg(&e4[idx4]);
                int b = idx4 * 4;
                if ((unsigned)r.x < (unsigned)n) g_rank[b + 0] = atomicAdd(&g_cnt[r.x], 1);
                if ((unsigned)r.y < (unsigned)n) g_rank[b + 1] = atomicAdd(&g_cnt[r.y], 1);
                if ((unsigned)r.z < (unsigned)n) g_rank[b + 2] = atomicAdd(&g_cnt[r.z], 1);
                if ((unsigned)r.w < (unsigned)n) g_rank[b + 3] = atomicAdd(&g_cnt[r.w], 1);
            } else if (idx4 == ne4) {
                for (int s = idx4 * 4; s < e; s++) {
                    int r = __ldg(&ei[s]);
                    if ((unsigned)r < (unsigned)n) g_rank[s] = atomicAdd(&g_cnt[r], 1);
                }
            }
        }
        return;
    }

    // ---------------- projection slices ----------------
    if (blockIdx.x >= nblk_proj) return;

    __half* sA = (__half*)sbuf;
    __half* sW = (__half*)(sbuf + 18432);
    float*  sC = (float*)sbuf;

    const float* in   = a.in[p];
    const float* W    = a.W[p];
    const float* bias = a.b[p];
    // output target: base table, row stride (bytes), byte offset, format
    char* obase;
    int ostride, ooff;
    bool as_half;
    switch (p) {
        case 0: obase = (char*)g_q;  ostride = 256;    ooff = 0;   as_half = true;  break; // q_alpha
        case 1: obase = g_kv;        ostride = KV_ROW; ooff = 0;   as_half = true;  break; // k_alpha
        case 2: obase = (char*)g_q;  ostride = 256;    ooff = 128; as_half = true;  break; // q_beta
        case 3: obase = g_kv;        ostride = KV_ROW; ooff = 128; as_half = true;  break; // k_beta
        case 4: obase = g_kv;        ostride = KV_ROW; ooff = 256; as_half = false; break; // v_t (fp32)
        default: obase = g_kv;       ostride = KV_ROW; ooff = 512; as_half = false; break; // v_x (fp32)
    }

    int base = blockIdx.x * 128;

    #pragma unroll
    for (int t = 0; t < 8; t++) {
        int idx = tid + t * 256;
        int row = idx >> 4, c4 = idx & 15;
        int g = base + row;
        float4 f = (g < n) ? ((const float4*)in)[(size_t)g * 16 + c4]
                           : make_float4(0.f, 0.f, 0.f, 0.f);
        __half2 h0 = __floats2half2_rn(f.x, f.y);
        __half2 h1 = __floats2half2_rn(f.z, f.w);
        __half2* d = (__half2*)&sA[row * LDA + c4 * 4];
        d[0] = h0; d[1] = h1;
    }
    #pragma unroll
    for (int t = 0; t < 4; t++) {
        int idx = tid + t * 256;
        int row = idx >> 4, c4 = idx & 15;
        float4 f = ((const float4*)W)[idx];
        __half2 h0 = __floats2half2_rn(f.x, f.y);
        __half2 h1 = __floats2half2_rn(f.z, f.w);
        __half2* d = (__half2*)&sW[row * LDW + c4 * 4];
        d[0] = h0; d[1] = h1;
    }
    __syncthreads();

    int w  = tid >> 5;
    int wm = w & 3, wn = w >> 2;

    wmma::fragment<wmma::accumulator, 16, 16, 16, float> c[2][2];
    #pragma unroll
    for (int i = 0; i < 2; i++)
        #pragma unroll
        for (int jj = 0; jj < 2; jj++)
            wmma::fill_fragment(c[i][jj], 0.f);

    #pragma unroll
    for (int k0 = 0; k0 < 64; k0 += 16) {
        wmma::fragment<wmma::matrix_a, 16, 16, 16, __half, wmma::row_major> af[2];
        wmma::fragment<wmma::matrix_b, 16, 16, 16, __half, wmma::col_major> bf[2];
        #pragma unroll
        for (int i = 0; i < 2; i++)
            wmma::load_matrix_sync(af[i], &sA[(wm * 32 + i * 16) * LDA + k0], LDA);
        #pragma unroll
        for (int jj = 0; jj < 2; jj++)
            wmma::load_matrix_sync(bf[jj], &sW[(wn * 32 + jj * 16) * LDW + k0], LDW);
        #pragma unroll
        for (int i = 0; i < 2; i++)
            #pragma unroll
            for (int jj = 0; jj < 2; jj++)
                wmma::mma_sync(c[i][jj], af[i], bf[jj], c[i][jj]);
    }
    __syncthreads();

    #pragma unroll
    for (int i = 0; i < 2; i++)
        #pragma unroll
        for (int jj = 0; jj < 2; jj++)
            wmma::store_matrix_sync(&sC[(wm * 32 + i * 16) * LDC + wn * 32 + jj * 16],
                                    c[i][jj], LDC, wmma::mem_row_major);
    __syncthreads();

    #pragma unroll
    for (int t = 0; t < 16; t++) {
        int i = tid + t * 256;
        int row = i >> 5, pr = i & 31;
        int g = base + row;
        if (g < n) {
            float f0 = sC[row * LDC + 2 * pr];
            float f1 = sC[row * LDC + 2 * pr + 1];
            if (bias) { f0 += bias[2 * pr]; f1 += bias[2 * pr + 1]; }
            char* rowp = obase + (size_t)g * ostride + ooff;
            if (as_half) {
                *(__half2*)(rowp + pr * 4) = __floats2half2_rn(f0, f1);
            } else {
                *(float2*)(rowp + pr * 8) = make_float2(f0, f1);
            }
        }
    }
}

// ---------------- kernel 2: one-shot atomic-ticket scan ----------------
__global__ __launch_bounds__(SCAN_BLK) void scan_ticket_kernel(int n) {
    __shared__ int s_w[8];
    __shared__ int s_tot;
    __shared__ int s_base;
    int tid = threadIdx.x;
    int i = blockIdx.x * SCAN_BLK + tid;
    int v = (i < n) ? g_cnt[i] : 0;
    if (i < n) g_cnt[i] = 0;

    int x = v;
    #pragma unroll
    for (int o = 1; o < 32; o <<= 1) {
        int t = __shfl_up_sync(0xFFFFFFFFu, x, o);
        if ((tid & 31) >= o) x += t;
    }
    if ((tid & 31) == 31) s_w[tid >> 5] = x;
    __syncthreads();
    if (tid < 8) {
        int w = s_w[tid];
        #pragma unroll
        for (int o = 1; o < 8; o <<= 1) {
            int t = __shfl_up_sync(0xFFu, w, o);
            if (tid >= o) w += t;
        }
        s_w[tid] = w;
        if (tid == 7) s_tot = w;
    }
    __syncthreads();
    int warp = tid >> 5;
    int woff = (warp == 0) ? 0 : s_w[warp - 1];
    int excl = woff + x - v;

    if (tid == 0) s_base = atomicAdd(&g_total, s_tot);
    __syncthreads();

    if (i < n) {
        int g = s_base + excl;
        g_start[i]  = g;
        g_cursor[i] = g + v;    // bucket end
    }
}

// ---------------- kernel 3: atomic-free scatter (stores byte offsets) ----
__global__ void scatter_kernel(const int* __restrict__ ei, int e, int n) {
    int i = blockIdx.x * blockDim.x + threadIdx.x;
    if (i >= e) return;
    int r = __ldg(&ei[i]);
    int c = __ldg(&ei[e + i]);
    if ((unsigned)r >= (unsigned)n || (unsigned)c >= (unsigned)n) return;
    int pos = __ldg(&g_start[r]) + __ldg(&g_rank[i]);
    g_sc[pos] = c * KV_ROW;   // byte offset of kv row
}

// ---------------- kernel 4: per-node gather + softmax + aggregate --------
// One warp per node, 2 edges/iter, 8-lane-group reduction (5 shfl / 2
// edges). g_sc holds byte offsets; v is fp32 in the kv row (no cvt in the
// accumulate path). Prefetch is UNGUARDED: slots past the bucket end hold a
// neighbor's offset or 0 — always a valid row; stale data gets weight 0.
__global__ __launch_bounds__(128) void node_kernel(float* __restrict__ out, int n) {
    int warp = (blockIdx.x * blockDim.x + threadIdx.x) >> 5;
    int lane = threadIdx.x & 31;
    if (warp >= n) return;
    int r = warp;

    int j    = g_start[r];
    int jend = g_cursor[r];

    int lane16 = lane & 15;
    int isB    = lane >> 4;           // 0: edge-A lanes, 1: edge-B lanes
    int srcA   = (lane & 16) >> 1;    // 0 or 8
    int srcB   = 16 + srcA;           // 16 or 24

    const char* kvb = (const char*)g_kv;
    int koff = lane16 * 16;           // 16B slice of the k part (256B)
    int voff = 256 + lane * 16;       // 16B slice of v: lanes<16 v_t, >=16 v_x

    uint4 qv = ((const uint4*)g_q)[(size_t)r * 16 + lane16];
    __half2 q0 = *(const __half2*)&qv.x;
    __half2 q1 = *(const __half2*)&qv.y;
    __half2 q2 = *(const __half2*)&qv.z;
    __half2 q3 = *(const __half2*)&qv.w;

    float4 acc = make_float4(0.f, 0.f, 0.f, 0.f);
    float  den = 0.f;

    // unguarded depth-1 prefetch
    int offA = __ldg(&g_sc[j]);
    int offB = __ldg(&g_sc[j + 1]);
    int offS = isB ? offB : offA;
    uint4  kP  = *(const uint4*)(kvb + offS + koff);
    float4 vAP = *(const float4*)(kvb + offA + voff);
    float4 vBP = *(const float4*)(kvb + offB + voff);

    while (j < jend) {
        uint4  kv = kP;
        float4 vA = vAP, vB = vBP;
        int rem = jend - j;
        int jn = j + 2;

        offA = __ldg(&g_sc[jn]);
        offB = __ldg(&g_sc[jn + 1]);
        offS = isB ? offB : offA;
        kP  = *(const uint4*)(kvb + offS + koff);
        vAP = *(const float4*)(kvb + offA + voff);
        vBP = *(const float4*)(kvb + offB + voff);
        j = jn;

        // 8-half dot fragment in half2, single cvt, fp32 combine
        __half2 d = __hmul2(q0, *(const __half2*)&kv.x);
        d = __hfma2(q1, *(const __half2*)&kv.y, d);
        d = __hfma2(q2, *(const __half2*)&kv.z, d);
        d = __hfma2(q3, *(const __half2*)&kv.w, d);
        float2 f = __half22float2(d);
        float p = f.x + f.y;

        // one 3-step reduce yields all four dots (8-lane groups)
        p += __shfl_xor_sync(0xFFFFFFFFu, p, 1);
        p += __shfl_xor_sync(0xFFFFFFFFu, p, 2);
        p += __shfl_xor_sync(0xFFFFFFFFu, p, 4);

        float ex = __expf(p * 0.125f);

        float wA = __shfl_sync(0xFFFFFFFFu, ex, srcA);
        float wB = __shfl_sync(0xFFFFFFFFu, ex, srcB);
        if (rem < 2) wB = 0.f;
        den += wA + wB;

        acc.x = fmaf(wA, vA.x, fmaf(wB, vB.x, acc.x));
        acc.y = fmaf(wA, vA.y, fmaf(wB, vB.y, acc.y));
        acc.z = fmaf(wA, vA.z, fmaf(wB, vB.z, acc.z));
        acc.w = fmaf(wA, vA.w, fmaf(wB, vB.w, acc.w));
    }

    float inv = (den > 0.f) ? __frcp_rn(den) : 0.f;
    acc.x *= inv; acc.y *= inv; acc.z *= inv; acc.w *= inv;

    int totD = n * D;
    if (lane < 16) {   // t-message -> out_t
        *(float4*)&out[totD + r * D + 4 * lane] = acc;
    } else {           // x-message -> out_x
        *(float4*)&out[r * D + 4 * (lane - 16)] = acc;
    }
}

// ---------------- launch ----------------
extern "C" void kernel_launch(void* const* d_in, const int* in_sizes, int n_in,
                              void* d_out, int out_size) {
    const float* x_src = (const float*)d_in[0];
    const float* x_tgt = (const float*)d_in[1];
    const float* t_src = (const float*)d_in[2];
    const float* t_tgt = (const float*)d_in[3];
    const int*   ei    = (const int*)d_in[4];
    const float* W_x  = (const float*)d_in[5];
    const float* W_t  = (const float*)d_in[6];
    const float* Ka_W = (const float*)d_in[7];
    const float* Ka_b = (const float*)d_in[8];
    const float* Qa_W = (const float*)d_in[9];
    const float* Qa_b = (const float*)d_in[10];
    const float* Kb_W = (const float*)d_in[11];
    const float* Kb_b = (const float*)d_in[12];
    const float* Qb_W = (const float*)d_in[13];
    const float* Qb_b = (const float*)d_in[14];

    int n = in_sizes[0] / D;      // 50000
    int e = in_sizes[4] / 2;      // 800000

    PArgs pa;
    pa.in[0] = t_tgt; pa.W[0] = Qa_W; pa.b[0] = Qa_b;    // q_alpha
    pa.in[1] = t_src; pa.W[1] = Ka_W; pa.b[1] = Ka_b;    // k_alpha
    pa.in[2] = x_tgt; pa.W[2] = Qb_W; pa.b[2] = Qb_b;    // q_beta
    pa.in[3] = x_src; pa.W[3] = Kb_W; pa.b[3] = Kb_b;    // k_beta
    pa.in[4] = t_src; pa.W[4] = W_t;  pa.b[4] = nullptr; // v_t
    pa.in[5] = x_src; pa.W[5] = W_x;  pa.b[5] = nullptr; // v_x

    int nblk_proj = (n + 127) / 128;                    // 391
    int nblk_hist = ((e + 7) / 8 + 255) / 256;          // 391
    int gx = nblk_proj > nblk_hist ? nblk_proj : nblk_hist;
    int nb = (n + SCAN_BLK - 1) / SCAN_BLK;             // 196

    proj_hist_kernel<<<dim3(gx, 7), 256>>>(pa, ei, n, e, nblk_proj);
    scan_ticket_kernel<<<nb, SCAN_BLK>>>(n);
    scatter_kernel<<<(e + 255) / 256, 256>>>(ei, e, n);
    node_kernel<<<(n * 32 + 127) / 128, 128>>>((float*)d_out, n);
}

// round 16
// speedup vs baseline: 1.1479x; 1.1479x over previous
#include <cuda_runtime.h>
#include <cuda_fp16.h>
#include <mma.h>
using namespace nvcuda;

#define D 64
#define N_MAX 50048
#define E_MAX 800000
#define SCAN_BLK 256

// ---------------- device scratch (static, allowed) ----------------
// g_q[node]  = [q_alpha(64) | q_beta(64)]                      (256B row)
// g_kv[node] = [k_alpha(64) | k_beta(64) | v_t(64) | v_x(64)]  (512B row)
__device__ __align__(16) __half g_q [N_MAX * 128];
__device__ __align__(16) __half g_kv[N_MAX * 256];

// CSR-style bucketing of edges by destination (row).
__device__ int g_cnt[N_MAX];      // in-degree (zero at load; scan re-zeros)
__device__ int g_start[N_MAX];    // bucket base
__device__ int g_cursor[N_MAX];   // bucket END (start + cnt), set by scan
__device__ int g_sc[E_MAX + 8];   // BYTE OFFSET of src node's kv row (c<<9); slack zeroed
__device__ int g_rank[E_MAX];     // within-bucket rank (from hist)
__device__ int g_total;           // ticket counter

// ---------------- kernel 1: projections via HMMA + fused histogram ------
struct PArgs {
    const float* in[6];
    const float* W[6];
    const float* b[6];
};

#define LDA 72
#define LDW 72
#define LDC 68

__global__ __launch_bounds__(256) void proj_hist_kernel(
    PArgs a, const int* __restrict__ ei, int n, int e, int nblk_proj) {
    __shared__ __align__(16) char sbuf[34816];

    int p   = blockIdx.y;
    int tid = threadIdx.x;

    // ---------------- histogram slice (hides under tensor work) ----------
    if (p == 6) {
        if (tid == 0 && blockIdx.x == 0) g_total = 0;
        int i = blockIdx.x * 256 + tid;       // thread handles 8 edges = 2 int4
        const int4* e4 = (const int4*)ei;
        int ne4 = e >> 2;
        #pragma unroll
        for (int t = 0; t < 2; t++) {
            int idx4 = i * 2 + t;
            if (idx4 < ne4) {
                int4 r = __ldg(&e4[idx4]);
                int b = idx4 * 4;
                if ((unsigned)r.x < (unsigned)n) g_rank[b + 0] = atomicAdd(&g_cnt[r.x], 1);
                if ((unsigned)r.y < (unsigned)n) g_rank[b + 1] = atomicAdd(&g_cnt[r.y], 1);
                if ((unsigned)r.z < (unsigned)n) g_rank[b + 2] = atomicAdd(&g_cnt[r.z], 1);
                if ((unsigned)r.w < (unsigned)n) g_rank[b + 3] = atomicAdd(&g_cnt[r.w], 1);
            } else if (idx4 == ne4) {
                for (int s = idx4 * 4; s < e; s++) {
                    int r = __ldg(&ei[s]);
                    if ((unsigned)r < (unsigned)n) g_rank[s] = atomicAdd(&g_cnt[r], 1);
                }
            }
        }
        return;
    }

    // ---------------- projection slices ----------------
    if (blockIdx.x >= nblk_proj) return;

    __half* sA = (__half*)sbuf;
    __half* sW = (__half*)(sbuf + 18432);
    float*  sC = (float*)sbuf;

    const float* in   = a.in[p];
    const float* W    = a.W[p];
    const float* bias = a.b[p];
    __half* outp;
    int coloff, stride;
    switch (p) {
        case 0: outp = g_q;  coloff = 0;   stride = 128; break;  // q_alpha
        case 1: outp = g_kv; coloff = 0;   stride = 256; break;  // k_alpha
        case 2: outp = g_q;  coloff = 64;  stride = 128; break;  // q_beta
        case 3: outp = g_kv; coloff = 64;  stride = 256; break;  // k_beta
        case 4: outp = g_kv; coloff = 128; stride = 256; break;  // v_t
        default: outp = g_kv; coloff = 192; stride = 256; break; // v_x
    }

    int base = blockIdx.x * 128;

    #pragma unroll
    for (int t = 0; t < 8; t++) {
        int idx = tid + t * 256;
        int row = idx >> 4, c4 = idx & 15;
        int g = base + row;
        float4 f = (g < n) ? ((const float4*)in)[(size_t)g * 16 + c4]
                           : make_float4(0.f, 0.f, 0.f, 0.f);
        __half2 h0 = __floats2half2_rn(f.x, f.y);
        __half2 h1 = __floats2half2_rn(f.z, f.w);
        __half2* d = (__half2*)&sA[row * LDA + c4 * 4];
        d[0] = h0; d[1] = h1;
    }
    #pragma unroll
    for (int t = 0; t < 4; t++) {
        int idx = tid + t * 256;
        int row = idx >> 4, c4 = idx & 15;
        float4 f = ((const float4*)W)[idx];
        __half2 h0 = __floats2half2_rn(f.x, f.y);
        __half2 h1 = __floats2half2_rn(f.z, f.w);
        __half2* d = (__half2*)&sW[row * LDW + c4 * 4];
        d[0] = h0; d[1] = h1;
    }
    __syncthreads();

    int w  = tid >> 5;
    int wm = w & 3, wn = w >> 2;

    wmma::fragment<wmma::accumulator, 16, 16, 16, float> c[2][2];
    #pragma unroll
    for (int i = 0; i < 2; i++)
        #pragma unroll
        for (int jj = 0; jj < 2; jj++)
            wmma::fill_fragment(c[i][jj], 0.f);

    #pragma unroll
    for (int k0 = 0; k0 < 64; k0 += 16) {
        wmma::fragment<wmma::matrix_a, 16, 16, 16, __half, wmma::row_major> af[2];
        wmma::fragment<wmma::matrix_b, 16, 16, 16, __half, wmma::col_major> bf[2];
        #pragma unroll
        for (int i = 0; i < 2; i++)
            wmma::load_matrix_sync(af[i], &sA[(wm * 32 + i * 16) * LDA + k0], LDA);
        #pragma unroll
        for (int jj = 0; jj < 2; jj++)
            wmma::load_matrix_sync(bf[jj], &sW[(wn * 32 + jj * 16) * LDW + k0], LDW);
        #pragma unroll
        for (int i = 0; i < 2; i++)
            #pragma unroll
            for (int jj = 0; jj < 2; jj++)
                wmma::mma_sync(c[i][jj], af[i], bf[jj], c[i][jj]);
    }
    __syncthreads();

    #pragma unroll
    for (int i = 0; i < 2; i++)
        #pragma unroll
        for (int jj = 0; jj < 2; jj++)
            wmma::store_matrix_sync(&sC[(wm * 32 + i * 16) * LDC + wn * 32 + jj * 16],
                                    c[i][jj], LDC, wmma::mem_row_major);
    __syncthreads();

    #pragma unroll
    for (int t = 0; t < 16; t++) {
        int i = tid + t * 256;
        int row = i >> 5, pr = i & 31;
        int g = base + row;
        if (g < n) {
            float f0 = sC[row * LDC + 2 * pr];
            float f1 = sC[row * LDC + 2 * pr + 1];
            if (bias) { f0 += bias[2 * pr]; f1 += bias[2 * pr + 1]; }
            *(__half2*)&outp[(size_t)g * stride + coloff + 2 * pr] =
                __floats2half2_rn(f0, f1);
        }
    }
}

// ---------------- kernel 2: one-shot atomic-ticket scan ----------------
__global__ __launch_bounds__(SCAN_BLK) void scan_ticket_kernel(int n) {
    __shared__ int s_w[8];
    __shared__ int s_tot;
    __shared__ int s_base;
    int tid = threadIdx.x;
    int i = blockIdx.x * SCAN_BLK + tid;
    int v = (i < n) ? g_cnt[i] : 0;
    if (i < n) g_cnt[i] = 0;

    int x = v;
    #pragma unroll
    for (int o = 1; o < 32; o <<= 1) {
        int t = __shfl_up_sync(0xFFFFFFFFu, x, o);
        if ((tid & 31) >= o) x += t;
    }
    if ((tid & 31) == 31) s_w[tid >> 5] = x;
    __syncthreads();
    if (tid < 8) {
        int w = s_w[tid];
        #pragma unroll
        for (int o = 1; o < 8; o <<= 1) {
            int t = __shfl_up_sync(0xFFu, w, o);
            if (tid >= o) w += t;
        }
        s_w[tid] = w;
        if (tid == 7) s_tot = w;
    }
    __syncthreads();
    int warp = tid >> 5;
    int woff = (warp == 0) ? 0 : s_w[warp - 1];
    int excl = woff + x - v;

    if (tid == 0) s_base = atomicAdd(&g_total, s_tot);
    __syncthreads();

    if (i < n) {
        int g = s_base + excl;
        g_start[i]  = g;
        g_cursor[i] = g + v;    // bucket end
    }
}

// ---------------- kernel 3: atomic-free scatter (stores byte offsets) ----
__global__ void scatter_kernel(const int* __restrict__ ei, int e, int n) {
    int i = blockIdx.x * blockDim.x + threadIdx.x;
    if (i >= e) return;
    int r = __ldg(&ei[i]);
    int c = __ldg(&ei[e + i]);
    if ((unsigned)r >= (unsigned)n || (unsigned)c >= (unsigned)n) return;
    int pos = __ldg(&g_start[r]) + __ldg(&g_rank[i]);
    g_sc[pos] = c << 9;       // byte offset of kv row (512B rows)
}

// ---------------- kernel 4: per-node gather + softmax + aggregate --------
// Exact R14 structure (regs=40, node=44.8us measured) with ONE change:
// prefetch is UNGUARDED. g_sc slack is zeroed (row 0 — always legal), slots
// past the bucket end load garbage that gets weight 0. Saves ~4 ISETP/SEL
// per iteration at zero register cost.
__global__ __launch_bounds__(128) void node_kernel(float* __restrict__ out, int n) {
    int warp = (blockIdx.x * blockDim.x + threadIdx.x) >> 5;
    int lane = threadIdx.x & 31;
    if (warp >= n) return;
    int r = warp;

    int j    = g_start[r];
    int jend = g_cursor[r];

    int lane16 = lane & 15;
    int isB    = lane >> 4;           // 0: edge-A lanes, 1: edge-B lanes
    int srcA   = (lane & 16) >> 1;    // 0 or 8
    int srcB   = 16 + srcA;           // 16 or 24

    const char* kvb = (const char*)g_kv;
    int koff = lane16 * 16;           // lane's 16B slice of the k part
    int voff = 256 + lane * 8;        // lane's 8B slice of the v part

    uint4 qv = ((const uint4*)g_q)[(size_t)r * 16 + lane16];
    __half2 q0 = *(const __half2*)&qv.x;
    __half2 q1 = *(const __half2*)&qv.y;
    __half2 q2 = *(const __half2*)&qv.z;
    __half2 q3 = *(const __half2*)&qv.w;

    float4 acc = make_float4(0.f, 0.f, 0.f, 0.f);
    float  den = 0.f;

    // unguarded depth-1 prefetch (slack slots are valid row-0 offsets)
    int offA = __ldg(&g_sc[j]);
    int offB = __ldg(&g_sc[j + 1]);
    int offS = isB ? offB : offA;
    uint4 kP  = *(const uint4*)(kvb + offS + koff);
    uint2 vAP = *(const uint2*)(kvb + offA + voff);
    uint2 vBP = *(const uint2*)(kvb + offB + voff);

    while (j < jend) {
        uint4 kv = kP;
        uint2 vA = vAP, vB = vBP;
        int rem = jend - j;
        int jn = j + 2;

        offA = __ldg(&g_sc[jn]);
        offB = __ldg(&g_sc[jn + 1]);
        offS = isB ? offB : offA;
        kP  = *(const uint4*)(kvb + offS + koff);
        vAP = *(const uint2*)(kvb + offA + voff);
        vBP = *(const uint2*)(kvb + offB + voff);
        j = jn;

        // 8-half dot fragment in half2, single cvt, fp32 combine
        __half2 d = __hmul2(q0, *(const __half2*)&kv.x);
        d = __hfma2(q1, *(const __half2*)&kv.y, d);
        d = __hfma2(q2, *(const __half2*)&kv.z, d);
        d = __hfma2(q3, *(const __half2*)&kv.w, d);
        float2 f = __half22float2(d);
        float p = f.x + f.y;

        // one 3-step reduce yields all four dots (8-lane groups)
        p += __shfl_xor_sync(0xFFFFFFFFu, p, 1);
        p += __shfl_xor_sync(0xFFFFFFFFu, p, 2);
        p += __shfl_xor_sync(0xFFFFFFFFu, p, 4);

        float ex = __expf(p * 0.125f);

        float wA = __shfl_sync(0xFFFFFFFFu, ex, srcA);
        float wB = __shfl_sync(0xFFFFFFFFu, ex, srcB);
        if (rem < 2) wB = 0.f;
        den += wA + wB;

        float2 va0 = __half22float2(*(const __half2*)&vA.x);
        float2 va1 = __half22float2(*(const __half2*)&vA.y);
        float2 vb0 = __half22float2(*(const __half2*)&vB.x);
        float2 vb1 = __half22float2(*(const __half2*)&vB.y);

        acc.x = fmaf(wA, va0.x, fmaf(wB, vb0.x, acc.x));
        acc.y = fmaf(wA, va0.y, fmaf(wB, vb0.y, acc.y));
        acc.z = fmaf(wA, va1.x, fmaf(wB, vb1.x, acc.z));
        acc.w = fmaf(wA, va1.y, fmaf(wB, vb1.y, acc.w));
    }

    float inv = (den > 0.f) ? __frcp_rn(den) : 0.f;
    acc.x *= inv; acc.y *= inv; acc.z *= inv; acc.w *= inv;

    int totD = n * D;
    if (lane < 16) {   // t-message -> out_t
        *(float4*)&out[totD + r * D + 4 * lane] = acc;
    } else {           // x-message -> out_x
        *(float4*)&out[r * D + 4 * (lane - 16)] = acc;
    }
}

// ---------------- launch ----------------
extern "C" void kernel_launch(void* const* d_in, const int* in_sizes, int n_in,
                              void* d_out, int out_size) {
    const float* x_src = (const float*)d_in[0];
    const float* x_tgt = (const float*)d_in[1];
    const float* t_src = (const float*)d_in[2];
    const float* t_tgt = (const float*)d_in[3];
    const int*   ei    = (const int*)d_in[4];
    const float* W_x  = (const float*)d_in[5];
    const float* W_t  = (const float*)d_in[6];
    const float* Ka_W = (const float*)d_in[7];
    const float* Ka_b = (const float*)d_in[8];
    const float* Qa_W = (const float*)d_in[9];
    const float* Qa_b = (const float*)d_in[10];
    const float* Kb_W = (const float*)d_in[11];
    const float* Kb_b = (const float*)d_in[12];
    const float* Qb_W = (const float*)d_in[13];
    const float* Qb_b = (const float*)d_in[14];

    int n = in_sizes[0] / D;      // 50000
    int e = in_sizes[4] / 2;      // 800000

    PArgs pa;
    pa.in[0] = t_tgt; pa.W[0] = Qa_W; pa.b[0] = Qa_b;    // q_alpha
    pa.in[1] = t_src; pa.W[1] = Ka_W; pa.b[1] = Ka_b;    // k_alpha
    pa.in[2] = x_tgt; pa.W[2] = Qb_W; pa.b[2] = Qb_b;    // q_beta
    pa.in[3] = x_src; pa.W[3] = Kb_W; pa.b[3] = Kb_b;    // k_beta
    pa.in[4] = t_src; pa.W[4] = W_t;  pa.b[4] = nullptr; // v_t
    pa.in[5] = x_src; pa.W[5] = W_x;  pa.b[5] = nullptr; // v_x

    int nblk_proj = (n + 127) / 128;                    // 391
    int nblk_hist = ((e + 7) / 8 + 255) / 256;          // 391
    int gx = nblk_proj > nblk_hist ? nblk_proj : nblk_hist;
    int nb = (n + SCAN_BLK - 1) / SCAN_BLK;             // 196

    proj_hist_kernel<<<dim3(gx, 7), 256>>>(pa, ei, n, e, nblk_proj);
    scan_ticket_kernel<<<nb, SCAN_BLK>>>(n);
    scatter_kernel<<<(e + 255) / 256, 256>>>(ei, e, n);
    node_kernel<<<(n * 32 + 127) / 128, 128>>>((float*)d_out, n);
}